// round 4
// baseline (speedup 1.0000x reference)
#include <cuda_runtime.h>
#include <math.h>
#include <float.h>

// Problem constants
#define Bv   8
#define Lv   4096
#define LP   4097          // L + 1 (bias token)
#define KDv  512
#define EDv  1024
#define DK   64            // KD / H
#define DV   128           // ED / H
#define BH   64            // B * H
#define KCHUNK   (LP * DK)          // floats per (b,h) key chunk in raw view
#define VCHUNK   (LP * DV)          // floats per (b,h) value chunk in raw view
#define KBATCH   (Lv * KDv)         // real key floats per batch
#define VBATCH   (Lv * EDv)         // real value floats per batch
#define NT   16                     // j-tiles for the AV kernel
#define TILE 257                    // ceil(4097 / 16)
#define NPAIR 2049                  // row-pairs per bh
#define SBLK  257                   // ceil(NPAIR / 8) blocks per bh in k_scores

// Scratch (allocation-free rule: __device__ globals)
__device__ float g_scores[BH * LP];           // ~1.05 MB raw scores
__device__ float g_partial[BH * NT * DV];     // 512 KB
__device__ float g_max[BH];
__device__ float g_sum[BH];
__device__ int   g_cnt_s[BH];                 // zero-init; self-resetting
__device__ int   g_cnt_b[Bv];                 // zero-init; self-resetting

// 256-thread block reduce (8 warps)
__device__ __forceinline__ float blk_reduce256(float v, float* sh, bool do_max) {
    int lane = threadIdx.x & 31, warp = threadIdx.x >> 5;
    #pragma unroll
    for (int o = 16; o > 0; o >>= 1) {
        float t = __shfl_xor_sync(0xffffffffu, v, o);
        v = do_max ? fmaxf(v, t) : (v + t);
    }
    if (lane == 0) sh[warp] = v;
    __syncthreads();
    if (warp == 0) {
        v = (lane < 8) ? sh[lane] : (do_max ? -FLT_MAX : 0.0f);
        #pragma unroll
        for (int o = 4; o > 0; o >>= 1) {
            float t = __shfl_xor_sync(0xffffffffu, v, o);
            v = do_max ? fmaxf(v, t) : (v + t);
        }
        if (lane == 0) sh[0] = v;
    }
    __syncthreads();
    v = sh[0];
    __syncthreads();
    return v;
}

// ---------------------------------------------------------------------------
// Kernel 1: scores[bh, j] = dot64(Q[h], K[bh,j,:]) * w[h,j] + bias[h,j]
// grid (SBLK, BH), 256 threads. One warp per PAIR of rows (R2-proven layout).
// Last block per bh computes softmax stats (max, sum-exp) from L2.
// ---------------------------------------------------------------------------
__global__ void k_scores(const float* __restrict__ keys,
                         const float* __restrict__ k_bias,
                         const float* __restrict__ query,
                         const float* __restrict__ sw,
                         const float* __restrict__ sb) {
    int bh   = blockIdx.y;
    int b    = bh >> 3;
    int h    = bh & 7;
    int warp = threadIdx.x >> 5;
    int lane = threadIdx.x & 31;
    int p    = blockIdx.x * 8 + warp;

    if (p < NPAIR) {
        int half = lane >> 4;          // which row of the pair
        int li   = lane & 15;          // float4 slot within the 64-float row
        int j    = p * 2 + half;
        int jc   = min(j, LP - 1);

        int f = h * KCHUNK + jc * DK + li * 4;
        const float* kp = (f >= KBATCH) ? (k_bias + (f - KBATCH))
                                        : (keys + b * KBATCH + f);
        float4 kv = __ldcs((const float4*)kp);
        float4 qv = *(const float4*)(query + h * DK + li * 4);
        float s = kv.x * qv.x + kv.y * qv.y + kv.z * qv.z + kv.w * qv.w;
        #pragma unroll
        for (int o = 8; o > 0; o >>= 1)
            s += __shfl_xor_sync(0xffffffffu, s, o);

        if (li == 0 && j < LP) {
            int wi = h * LP + j;
            g_scores[bh * LP + j] = s * __ldg(sw + wi) + __ldg(sb + wi);
        }
    }

    // ---- last-block-per-bh softmax stats epilogue ----
    __threadfence();
    __syncthreads();
    __shared__ int lastFlag;
    if (threadIdx.x == 0)
        lastFlag = (atomicAdd(&g_cnt_s[bh], 1) == SBLK - 1);
    __syncthreads();
    if (!lastFlag) return;
    __threadfence();

    __shared__ float sh[8];
    const float* row = g_scores + bh * LP;

    float v[17];
    float m = -FLT_MAX;
    #pragma unroll
    for (int k = 0; k < 17; k++) {
        int j = threadIdx.x + k * 256;
        v[k] = (j < LP) ? __ldcg(row + j) : -FLT_MAX;
        m = fmaxf(m, v[k]);
    }
    m = blk_reduce256(m, sh, true);

    float ssum = 0.0f;
    #pragma unroll
    for (int k = 0; k < 17; k++) {
        int j = threadIdx.x + k * 256;
        if (j < LP) ssum += expf(v[k] - m);
    }
    ssum = blk_reduce256(ssum, sh, false);

    if (threadIdx.x == 0) {
        g_max[bh] = m;
        g_sum[bh] = ssum;
        g_cnt_s[bh] = 0;          // reset for next graph replay
    }
}

// ---------------------------------------------------------------------------
// Kernel 2: partial[bh,tile,d] = sum_{j in tile} exp(s[bh,j]-m) * V[bh,j,d]
// grid (NT, BH), 256 threads = 8 warps; warps interleave rows mod 8.
// Last block per BATCH performs the partial reduce + normalize + LayerNorm.
// ---------------------------------------------------------------------------
__global__ void k_av(const float* __restrict__ values,
                     const float* __restrict__ v_bias,
                     const float* __restrict__ gamma,
                     const float* __restrict__ beta,
                     float* __restrict__ out) {
    int tile = blockIdx.x;
    int bh   = blockIdx.y;
    int b = bh >> 3, h = bh & 7;
    int r8 = threadIdx.x >> 5;
    int c  = threadIdx.x & 31;

    const float* p = g_scores + bh * LP;
    float m = g_max[bh];               // cross-kernel: L1 flushed at launch
    int j0 = tile * TILE;
    int j1 = min(j0 + TILE, LP);

    float4 acc = make_float4(0.f, 0.f, 0.f, 0.f);
    #pragma unroll 4
    for (int j = j0 + r8; j < j1; j += 8) {
        float pj = expf(__ldg(p + j) - m);
        int f = h * VCHUNK + j * DV;
        const float* vrow = (f >= VBATCH) ? (v_bias + (f - VBATCH))
                                          : (values + b * VBATCH + f);
        float4 vv = __ldcs((const float4*)(vrow + c * 4));
        acc.x += pj * vv.x;
        acc.y += pj * vv.y;
        acc.z += pj * vv.z;
        acc.w += pj * vv.w;
    }

    __shared__ float4 red[8][32];
    red[r8][c] = acc;
    __syncthreads();
    if (r8 == 0) {
        float4 a = red[0][c];
        #pragma unroll
        for (int w = 1; w < 8; w++) {
            float4 x = red[w][c];
            a.x += x.x; a.y += x.y; a.z += x.z; a.w += x.w;
        }
        *(float4*)(g_partial + (bh * NT + tile) * DV + c * 4) = a;
    }

    // ---- last-block-per-batch LayerNorm epilogue ----
    __threadfence();
    __syncthreads();
    __shared__ int lastFlag;
    if (threadIdx.x == 0)
        lastFlag = (atomicAdd(&g_cnt_b[b], 1) == NT * 8 - 1);
    __syncthreads();
    if (!lastFlag) return;
    __threadfence();

    __shared__ float sh_s[8];
    __shared__ float sh_q[8];
    int t  = threadIdx.x;           // 0..255, each owns 4 consecutive dims
    int D  = t * 4;
    int hh = t >> 5;
    int dd = D & 127;
    int bh2 = b * 8 + hh;

    const float* pp = g_partial + bh2 * (NT * DV) + dd;
    float4 a = make_float4(0.f, 0.f, 0.f, 0.f);
    #pragma unroll
    for (int k = 0; k < NT; k++) {
        float4 x = __ldcg((const float4*)(pp + k * DV));
        a.x += x.x; a.y += x.y; a.z += x.z; a.w += x.w;
    }
    float invS = 1.0f / g_sum[bh2];
    a.x *= invS; a.y *= invS; a.z *= invS; a.w *= invS;

    float s = a.x + a.y + a.z + a.w;
    float q = a.x * a.x + a.y * a.y + a.z * a.z + a.w * a.w;
    int lane = t & 31, warp = t >> 5;
    #pragma unroll
    for (int o = 16; o > 0; o >>= 1) {
        s += __shfl_xor_sync(0xffffffffu, s, o);
        q += __shfl_xor_sync(0xffffffffu, q, o);
    }
    if (lane == 0) { sh_s[warp] = s; sh_q[warp] = q; }
    __syncthreads();
    if (warp == 0 && lane < 8) {
        s = sh_s[lane];
        q = sh_q[lane];
        #pragma unroll
        for (int o = 4; o > 0; o >>= 1) {
            s += __shfl_xor_sync(0x000000ffu, s, o);
            q += __shfl_xor_sync(0x000000ffu, q, o);
        }
        if (lane == 0) { sh_s[0] = s; sh_q[0] = q; }
    }
    __syncthreads();
    float mean = sh_s[0] * (1.0f / EDv);
    float var  = sh_q[0] * (1.0f / EDv) - mean * mean;
    float inv  = rsqrtf(var + 1e-5f);

    float4 gm = *(const float4*)(gamma + D);
    float4 bt = *(const float4*)(beta + D);
    float4 o4;
    o4.x = (a.x - mean) * inv * gm.x + bt.x;
    o4.y = (a.y - mean) * inv * gm.y + bt.y;
    o4.z = (a.z - mean) * inv * gm.z + bt.z;
    o4.w = (a.w - mean) * inv * gm.w + bt.w;
    *(float4*)(out + b * EDv + D) = o4;

    if (t == 0) g_cnt_b[b] = 0;     // reset for next graph replay
}

// ---------------------------------------------------------------------------
// Launch: inputs in metadata order:
// keys, values, query, k_bias, v_bias, softmax_weight, softmax_bias, gamma, beta
// ---------------------------------------------------------------------------
extern "C" void kernel_launch(void* const* d_in, const int* in_sizes, int n_in,
                              void* d_out, int out_size) {
    const float* keys   = (const float*)d_in[0];
    const float* values = (const float*)d_in[1];
    const float* query  = (const float*)d_in[2];
    const float* k_bias = (const float*)d_in[3];
    const float* v_bias = (const float*)d_in[4];
    const float* sw     = (const float*)d_in[5];
    const float* sb     = (const float*)d_in[6];
    const float* gamma  = (const float*)d_in[7];
    const float* beta   = (const float*)d_in[8];
    float* out = (float*)d_out;

    dim3 g1(SBLK, BH);
    k_scores<<<g1, 256>>>(keys, k_bias, query, sw, sb);

    dim3 g2(NT, BH);
    k_av<<<g2, 256>>>(values, v_bias, gamma, beta, out);
}

// round 5
// speedup vs baseline: 1.2768x; 1.2768x over previous
#include <cuda_runtime.h>
#include <math.h>
#include <float.h>

// Problem constants
#define Bv   8
#define Lv   4096
#define LP   4097          // L + 1 (bias token)
#define KDv  512
#define EDv  1024
#define DK   64            // KD / H
#define DV   128           // ED / H
#define BH   64            // B * H
#define KCHUNK   (LP * DK)          // floats per (b,h) key chunk in raw view
#define VCHUNK   (LP * DV)          // floats per (b,h) value chunk in raw view
#define KBATCH   (Lv * KDv)         // real key floats per batch
#define VBATCH   (Lv * EDv)         // real value floats per batch
#define NT   16                     // j-tiles for the AV kernel
#define TILE 257                    // ceil(4097 / 16)
#define ROWS_PER_BLK 32             // k_scores: 8 warps x 4 rows
#define SBLK 129                    // ceil(4097 / 32) blocks per bh

// Scratch (allocation-free rule: __device__ globals)
__device__ float g_probs[BH * LP];            // unnormalized exp(scores), ~1.05 MB
__device__ float g_bsum[BH * SBLK];           // per-block partial sum-of-exp
__device__ float g_partial[BH * NT * DV];     // 512 KB AV partials

// ---------------------------------------------------------------------------
// Kernel 1: p[bh,j] = exp(dot64(Q[h],K[bh,j,:]) * w[h,j] + bias[h,j])
// grid (SBLK, BH), 256 threads. Warp handles 4 rows (two pairs), both key
// loads front-batched (MLP=2). Block writes its local sum-of-exp (no atomics).
// ---------------------------------------------------------------------------
__global__ void k_scores(const float* __restrict__ keys,
                         const float* __restrict__ k_bias,
                         const float* __restrict__ query,
                         const float* __restrict__ sw,
                         const float* __restrict__ sb) {
    int bh   = blockIdx.y;
    int b    = bh >> 3;
    int h    = bh & 7;
    int warp = threadIdx.x >> 5;
    int lane = threadIdx.x & 31;

    int half = lane >> 4;              // row parity within a pair
    int li   = lane & 15;              // float4 slot within 64-float row
    int j0   = blockIdx.x * ROWS_PER_BLK + warp * 4;   // first of 4 rows

    float4 qv = *(const float4*)(query + h * DK + li * 4);

    // front-batched loads for the two pairs
    float4 kv[2];
    int jj[2];
    #pragma unroll
    for (int i = 0; i < 2; i++) {
        int j  = j0 + 2 * i + half;
        jj[i]  = j;
        int jc = min(j, LP - 1);
        int f  = h * KCHUNK + jc * DK + li * 4;
        const float* kp = (f >= KBATCH) ? (k_bias + (f - KBATCH))
                                        : (keys + b * KBATCH + f);
        kv[i] = __ldcs((const float4*)kp);
    }

    float wsum = 0.0f;                 // warp-local sum of exps (on li==0 lanes)
    #pragma unroll
    for (int i = 0; i < 2; i++) {
        float s = kv[i].x * qv.x + kv[i].y * qv.y + kv[i].z * qv.z + kv[i].w * qv.w;
        #pragma unroll
        for (int o = 8; o > 0; o >>= 1)
            s += __shfl_xor_sync(0xffffffffu, s, o);
        int j = jj[i];
        if (j < LP) {
            int wi = h * LP + j;
            float e = expf(s * __ldg(sw + wi) + __ldg(sb + wi));
            if (li == 0) {
                g_probs[bh * LP + j] = e;
                wsum += e;
            }
        }
    }

    // block sum of exps (deterministic; only lanes 0 and 16 hold nonzero)
    #pragma unroll
    for (int o = 16; o > 0; o >>= 1)
        wsum += __shfl_xor_sync(0xffffffffu, wsum, o);
    __shared__ float shs[8];
    if (lane == 0) shs[warp] = wsum;
    __syncthreads();
    if (threadIdx.x == 0) {
        float t = 0.0f;
        #pragma unroll
        for (int w = 0; w < 8; w++) t += shs[w];
        g_bsum[bh * SBLK + blockIdx.x] = t;
    }
}

// ---------------------------------------------------------------------------
// Kernel 2: partial[bh,tile,d] = sum_{j in tile} p[bh,j] * V[bh,j,d]
// grid (NT, BH), 256 threads = 8 warps; warps interleave rows mod 8.
// Unroll x2 with front-batched loads (MLP>=2 per thread).
// ---------------------------------------------------------------------------
__global__ void k_av(const float* __restrict__ values,
                     const float* __restrict__ v_bias) {
    int tile = blockIdx.x;
    int bh   = blockIdx.y;
    int b = bh >> 3, h = bh & 7;
    int r8 = threadIdx.x >> 5;
    int c  = threadIdx.x & 31;

    const float* p = g_probs + bh * LP;
    int j0 = tile * TILE;
    int j1 = min(j0 + TILE, LP);

    float4 acc = make_float4(0.f, 0.f, 0.f, 0.f);
    int j = j0 + r8;
    for (; j + 8 < j1; j += 16) {
        float pa = __ldg(p + j);
        float pb = __ldg(p + j + 8);
        int fa = h * VCHUNK + j * DV;
        int fb = fa + 8 * DV;
        const float* ra = (fa >= VBATCH) ? (v_bias + (fa - VBATCH))
                                         : (values + b * VBATCH + fa);
        const float* rb = (fb >= VBATCH) ? (v_bias + (fb - VBATCH))
                                         : (values + b * VBATCH + fb);
        float4 va = __ldcs((const float4*)(ra + c * 4));
        float4 vb = __ldcs((const float4*)(rb + c * 4));
        acc.x += pa * va.x + pb * vb.x;
        acc.y += pa * va.y + pb * vb.y;
        acc.z += pa * va.z + pb * vb.z;
        acc.w += pa * va.w + pb * vb.w;
    }
    if (j < j1) {
        float pa = __ldg(p + j);
        int fa = h * VCHUNK + j * DV;
        const float* ra = (fa >= VBATCH) ? (v_bias + (fa - VBATCH))
                                         : (values + b * VBATCH + fa);
        float4 va = __ldcs((const float4*)(ra + c * 4));
        acc.x += pa * va.x;
        acc.y += pa * va.y;
        acc.z += pa * va.z;
        acc.w += pa * va.w;
    }

    __shared__ float4 red[8][32];
    red[r8][c] = acc;
    __syncthreads();
    if (r8 == 0) {
        float4 a = red[0][c];
        #pragma unroll
        for (int w = 1; w < 8; w++) {
            float4 x = red[w][c];
            a.x += x.x; a.y += x.y; a.z += x.z; a.w += x.w;
        }
        *(float4*)(g_partial + (bh * NT + tile) * DV + c * 4) = a;
    }
}

// ---------------------------------------------------------------------------
// Kernel 3: S[bh] = sum of block sums; reduce NT partials, /S, LayerNorm.
// One block of 256 threads per batch.
// ---------------------------------------------------------------------------
__global__ void k_ln(const float* __restrict__ gamma,
                     const float* __restrict__ beta,
                     float* __restrict__ out) {
    __shared__ float sh_invS[8];
    __shared__ float sh_s[8];
    __shared__ float sh_q[8];
    int b = blockIdx.x;
    int t = threadIdx.x;            // 0..255
    int lane = t & 31, warp = t >> 5;

    // Phase A: per-head sum of exps (warp w -> head w), deterministic order
    {
        const float* bs = g_bsum + (b * 8 + warp) * SBLK;
        float s = 0.0f;
        #pragma unroll
        for (int k = 0; k < 5; k++) {
            int i = lane + k * 32;
            if (i < SBLK) s += bs[i];
        }
        #pragma unroll
        for (int o = 16; o > 0; o >>= 1)
            s += __shfl_xor_sync(0xffffffffu, s, o);
        if (lane == 0) sh_invS[warp] = 1.0f / s;
    }
    __syncthreads();

    // Phase B: reduce partials (float4, MLP=NT), normalize, LayerNorm
    int D  = t * 4;                 // first owned embed dim
    int hh = t >> 5;
    int dd = D & 127;
    int bh = b * 8 + hh;

    const float* pp = g_partial + bh * (NT * DV) + dd;
    float4 a = make_float4(0.f, 0.f, 0.f, 0.f);
    #pragma unroll
    for (int k = 0; k < NT; k++) {
        float4 x = *(const float4*)(pp + k * DV);
        a.x += x.x; a.y += x.y; a.z += x.z; a.w += x.w;
    }
    float invS = sh_invS[hh];
    a.x *= invS; a.y *= invS; a.z *= invS; a.w *= invS;

    float s = a.x + a.y + a.z + a.w;
    float q = a.x * a.x + a.y * a.y + a.z * a.z + a.w * a.w;
    #pragma unroll
    for (int o = 16; o > 0; o >>= 1) {
        s += __shfl_xor_sync(0xffffffffu, s, o);
        q += __shfl_xor_sync(0xffffffffu, q, o);
    }
    if (lane == 0) { sh_s[warp] = s; sh_q[warp] = q; }
    __syncthreads();
    if (warp == 0 && lane < 8) {
        s = sh_s[lane];
        q = sh_q[lane];
        #pragma unroll
        for (int o = 4; o > 0; o >>= 1) {
            s += __shfl_xor_sync(0x000000ffu, s, o);
            q += __shfl_xor_sync(0x000000ffu, q, o);
        }
        if (lane == 0) { sh_s[0] = s; sh_q[0] = q; }
    }
    __syncthreads();
    float mean = sh_s[0] * (1.0f / EDv);
    float var  = sh_q[0] * (1.0f / EDv) - mean * mean;
    float inv  = rsqrtf(var + 1e-5f);

    float4 gm = *(const float4*)(gamma + D);
    float4 bt = *(const float4*)(beta + D);
    float4 o4;
    o4.x = (a.x - mean) * inv * gm.x + bt.x;
    o4.y = (a.y - mean) * inv * gm.y + bt.y;
    o4.z = (a.z - mean) * inv * gm.z + bt.z;
    o4.w = (a.w - mean) * inv * gm.w + bt.w;
    *(float4*)(out + b * EDv + D) = o4;
}

// ---------------------------------------------------------------------------
// Launch: inputs in metadata order:
// keys, values, query, k_bias, v_bias, softmax_weight, softmax_bias, gamma, beta
// ---------------------------------------------------------------------------
extern "C" void kernel_launch(void* const* d_in, const int* in_sizes, int n_in,
                              void* d_out, int out_size) {
    const float* keys   = (const float*)d_in[0];
    const float* values = (const float*)d_in[1];
    const float* query  = (const float*)d_in[2];
    const float* k_bias = (const float*)d_in[3];
    const float* v_bias = (const float*)d_in[4];
    const float* sw     = (const float*)d_in[5];
    const float* sb     = (const float*)d_in[6];
    const float* gamma  = (const float*)d_in[7];
    const float* beta   = (const float*)d_in[8];
    float* out = (float*)d_out;

    dim3 g1(SBLK, BH);
    k_scores<<<g1, 256>>>(keys, k_bias, query, sw, sb);

    dim3 g2(NT, BH);
    k_av<<<g2, 256>>>(values, v_bias);

    k_ln<<<Bv, 256>>>(gamma, beta, out);
}

// round 6
// speedup vs baseline: 1.3645x; 1.0687x over previous
#include <cuda_runtime.h>
#include <math.h>
#include <float.h>

// Problem constants
#define Bv   8
#define Lv   4096
#define LP   4097          // L + 1 (bias token)
#define KDv  512
#define EDv  1024
#define DK   64            // KD / H
#define DV   128           // ED / H
#define BH   64            // B * H
#define KCHUNK   (LP * DK)          // floats per (b,h) key chunk in raw view
#define VCHUNK   (LP * DV)          // floats per (b,h) value chunk in raw view
#define KBATCH   (Lv * KDv)         // real key floats per batch
#define VBATCH   (Lv * EDv)         // real value floats per batch
#define KBATCH4  (KBATCH / 4)
#define NT   16                     // j-tiles for the AV kernel
#define TILE 257                    // ceil(4097 / 16)
#define RPB  128                    // k_scores rows per block
#define SBLK 33                     // ceil(4097 / 128) blocks per bh

// Scratch (allocation-free rule: __device__ globals)
__device__ float g_probs[BH * LP];            // unnormalized exp(scores)
__device__ float g_bsum[BH * SBLK];           // per-block partial sum-of-exp
__device__ float g_partial[BH * NT * DV];     // 512 KB AV partials

// ---------------------------------------------------------------------------
// Kernel 1: p[bh,j] = exp(dot64(Q[h],K[bh,j,:]) * w[h,j] + bias[h,j])
// grid (SBLK, BH), 128 threads. Stage 128 rows (32KB) in smem coalesced,
// then thread t computes the full dot for row t from smem (no shuffles).
// ---------------------------------------------------------------------------
__global__ void __launch_bounds__(128) k_scores(
        const float* __restrict__ keys,
        const float* __restrict__ k_bias,
        const float* __restrict__ query,
        const float* __restrict__ sw,
        const float* __restrict__ sb) {
    __shared__ float4 sk[RPB][17];      // padded: conflict-free LDS.128
    __shared__ float4 sq[16];
    __shared__ float  shs[4];

    int bh = blockIdx.y;
    int b  = bh >> 3;
    int h  = bh & 7;
    int t  = threadIdx.x;
    int j0 = blockIdx.x * RPB;

    // stage query row (256B)
    if (t < 16) sq[t] = *((const float4*)(query + h * DK) + t);

    // stage 128 key rows, fully coalesced, per-float4 bias-region select
    int fbase4 = (h * KCHUNK) >> 2;     // float4 offset of head chunk
    const float4* kb4 = (const float4*)keys + (size_t)b * KBATCH4;
    const float4* bb4 = (const float4*)k_bias;
    #pragma unroll
    for (int i = 0; i < 16; i++) {
        int flat = t + i * 128;         // 0..2047 float4 within the block tile
        int row  = flat >> 4;
        int c4   = flat & 15;
        int jc   = min(j0 + row, LP - 1);
        int f4   = fbase4 + jc * 16 + c4;
        const float4* src = (f4 >= KBATCH4) ? (bb4 + (f4 - KBATCH4)) : (kb4 + f4);
        sk[row][c4] = __ldcs(src);
    }
    __syncthreads();

    // thread t owns row t: full dot64 from smem, 4 accumulators
    int j = j0 + t;
    float e = 0.0f;
    if (j < LP) {
        float a0 = 0.f, a1 = 0.f, a2 = 0.f, a3 = 0.f;
        #pragma unroll
        for (int k = 0; k < 16; k += 4) {
            float4 x0 = sk[t][k],     q0 = sq[k];
            float4 x1 = sk[t][k + 1], q1 = sq[k + 1];
            float4 x2 = sk[t][k + 2], q2 = sq[k + 2];
            float4 x3 = sk[t][k + 3], q3 = sq[k + 3];
            a0 += x0.x * q0.x + x0.y * q0.y + x0.z * q0.z + x0.w * q0.w;
            a1 += x1.x * q1.x + x1.y * q1.y + x1.z * q1.z + x1.w * q1.w;
            a2 += x2.x * q2.x + x2.y * q2.y + x2.z * q2.z + x2.w * q2.w;
            a3 += x3.x * q3.x + x3.y * q3.y + x3.z * q3.z + x3.w * q3.w;
        }
        float s  = (a0 + a1) + (a2 + a3);
        int   wi = h * LP + j;
        e = expf(s * __ldg(sw + wi) + __ldg(sb + wi));
        g_probs[bh * LP + j] = e;       // coalesced: consecutive t -> consecutive j
    }

    // block sum of exps (deterministic)
    int lane = t & 31, warp = t >> 5;
    float wsum = e;
    #pragma unroll
    for (int o = 16; o > 0; o >>= 1)
        wsum += __shfl_xor_sync(0xffffffffu, wsum, o);
    if (lane == 0) shs[warp] = wsum;
    __syncthreads();
    if (t == 0)
        g_bsum[bh * SBLK + blockIdx.x] = (shs[0] + shs[1]) + (shs[2] + shs[3]);
}

// ---------------------------------------------------------------------------
// Kernel 2: partial[bh,tile,d] = sum_{j in tile} p[bh,j] * V[bh,j,d]
// grid (NT, BH), 256 threads = 8 warps; warps interleave rows mod 8.
// Unroll x4 with front-batched loads (MLP=4+ per thread).
// ---------------------------------------------------------------------------
__global__ void k_av(const float* __restrict__ values,
                     const float* __restrict__ v_bias) {
    int tile = blockIdx.x;
    int bh   = blockIdx.y;
    int b = bh >> 3, h = bh & 7;
    int r8 = threadIdx.x >> 5;
    int c  = threadIdx.x & 31;

    const float* p = g_probs + bh * LP;
    int j0 = tile * TILE;
    int j1 = min(j0 + TILE, LP);

    float4 acc = make_float4(0.f, 0.f, 0.f, 0.f);
    int j = j0 + r8;
    for (; j + 24 < j1; j += 32) {
        float p0 = __ldg(p + j);
        float p1 = __ldg(p + j + 8);
        float p2 = __ldg(p + j + 16);
        float p3 = __ldg(p + j + 24);
        int f0 = h * VCHUNK + j * DV;
        int f1 = f0 + 8 * DV, f2 = f0 + 16 * DV, f3 = f0 + 24 * DV;
        const float* r0 = (f0 >= VBATCH) ? (v_bias + (f0 - VBATCH)) : (values + b * VBATCH + f0);
        const float* r1 = (f1 >= VBATCH) ? (v_bias + (f1 - VBATCH)) : (values + b * VBATCH + f1);
        const float* r2 = (f2 >= VBATCH) ? (v_bias + (f2 - VBATCH)) : (values + b * VBATCH + f2);
        const float* r3 = (f3 >= VBATCH) ? (v_bias + (f3 - VBATCH)) : (values + b * VBATCH + f3);
        float4 v0 = __ldcs((const float4*)(r0 + c * 4));
        float4 v1 = __ldcs((const float4*)(r1 + c * 4));
        float4 v2 = __ldcs((const float4*)(r2 + c * 4));
        float4 v3 = __ldcs((const float4*)(r3 + c * 4));
        acc.x += p0 * v0.x + p1 * v1.x + p2 * v2.x + p3 * v3.x;
        acc.y += p0 * v0.y + p1 * v1.y + p2 * v2.y + p3 * v3.y;
        acc.z += p0 * v0.z + p1 * v1.z + p2 * v2.z + p3 * v3.z;
        acc.w += p0 * v0.w + p1 * v1.w + p2 * v2.w + p3 * v3.w;
    }
    for (; j < j1; j += 8) {
        float pa = __ldg(p + j);
        int fa = h * VCHUNK + j * DV;
        const float* ra = (fa >= VBATCH) ? (v_bias + (fa - VBATCH)) : (values + b * VBATCH + fa);
        float4 va = __ldcs((const float4*)(ra + c * 4));
        acc.x += pa * va.x;
        acc.y += pa * va.y;
        acc.z += pa * va.z;
        acc.w += pa * va.w;
    }

    __shared__ float4 red[8][32];
    red[r8][c] = acc;
    __syncthreads();
    if (r8 == 0) {
        float4 a = red[0][c];
        #pragma unroll
        for (int w = 1; w < 8; w++) {
            float4 x = red[w][c];
            a.x += x.x; a.y += x.y; a.z += x.z; a.w += x.w;
        }
        *(float4*)(g_partial + (bh * NT + tile) * DV + c * 4) = a;
    }
}

// ---------------------------------------------------------------------------
// Kernel 3: S[bh] = sum of block sums; reduce NT partials, /S, LayerNorm.
// One block of 256 threads per batch.
// ---------------------------------------------------------------------------
__global__ void k_ln(const float* __restrict__ gamma,
                     const float* __restrict__ beta,
                     float* __restrict__ out) {
    __shared__ float sh_invS[8];
    __shared__ float sh_s[8];
    __shared__ float sh_q[8];
    int b = blockIdx.x;
    int t = threadIdx.x;            // 0..255
    int lane = t & 31, warp = t >> 5;

    // Phase A: per-head sum of exps (warp w -> head w)
    {
        const float* bs = g_bsum + (b * 8 + warp) * SBLK;
        float s = (lane < SBLK) ? bs[lane] : 0.0f;
        if (lane + 32 < SBLK) s += bs[lane + 32];
        #pragma unroll
        for (int o = 16; o > 0; o >>= 1)
            s += __shfl_xor_sync(0xffffffffu, s, o);
        if (lane == 0) sh_invS[warp] = 1.0f / s;
    }
    __syncthreads();

    // Phase B: reduce partials (float4, MLP=NT), normalize, LayerNorm
    int D  = t * 4;
    int hh = t >> 5;
    int dd = D & 127;
    int bh = b * 8 + hh;

    const float* pp = g_partial + bh * (NT * DV) + dd;
    float4 a = make_float4(0.f, 0.f, 0.f, 0.f);
    #pragma unroll
    for (int k = 0; k < NT; k++) {
        float4 x = *(const float4*)(pp + k * DV);
        a.x += x.x; a.y += x.y; a.z += x.z; a.w += x.w;
    }
    float invS = sh_invS[hh];
    a.x *= invS; a.y *= invS; a.z *= invS; a.w *= invS;

    float s = a.x + a.y + a.z + a.w;
    float q = a.x * a.x + a.y * a.y + a.z * a.z + a.w * a.w;
    #pragma unroll
    for (int o = 16; o > 0; o >>= 1) {
        s += __shfl_xor_sync(0xffffffffu, s, o);
        q += __shfl_xor_sync(0xffffffffu, q, o);
    }
    if (lane == 0) { sh_s[warp] = s; sh_q[warp] = q; }
    __syncthreads();
    if (warp == 0 && lane < 8) {
        s = sh_s[lane];
        q = sh_q[lane];
        #pragma unroll
        for (int o = 4; o > 0; o >>= 1) {
            s += __shfl_xor_sync(0x000000ffu, s, o);
            q += __shfl_xor_sync(0x000000ffu, q, o);
        }
        if (lane == 0) { sh_s[0] = s; sh_q[0] = q; }
    }
    __syncthreads();
    float mean = sh_s[0] * (1.0f / EDv);
    float var  = sh_q[0] * (1.0f / EDv) - mean * mean;
    float inv  = rsqrtf(var + 1e-5f);

    float4 gm = *(const float4*)(gamma + D);
    float4 bt = *(const float4*)(beta + D);
    float4 o4;
    o4.x = (a.x - mean) * inv * gm.x + bt.x;
    o4.y = (a.y - mean) * inv * gm.y + bt.y;
    o4.z = (a.z - mean) * inv * gm.z + bt.z;
    o4.w = (a.w - mean) * inv * gm.w + bt.w;
    *(float4*)(out + b * EDv + D) = o4;
}

// ---------------------------------------------------------------------------
// Launch: inputs in metadata order:
// keys, values, query, k_bias, v_bias, softmax_weight, softmax_bias, gamma, beta
// ---------------------------------------------------------------------------
extern "C" void kernel_launch(void* const* d_in, const int* in_sizes, int n_in,
                              void* d_out, int out_size) {
    const float* keys   = (const float*)d_in[0];
    const float* values = (const float*)d_in[1];
    const float* query  = (const float*)d_in[2];
    const float* k_bias = (const float*)d_in[3];
    const float* v_bias = (const float*)d_in[4];
    const float* sw     = (const float*)d_in[5];
    const float* sb     = (const float*)d_in[6];
    const float* gamma  = (const float*)d_in[7];
    const float* beta   = (const float*)d_in[8];
    float* out = (float*)d_out;

    dim3 g1(SBLK, BH);
    k_scores<<<g1, 128>>>(keys, k_bias, query, sw, sb);

    dim3 g2(NT, BH);
    k_av<<<g2, 256>>>(values, v_bias);

    k_ln<<<Bv, 256>>>(gamma, beta, out);
}

// round 7
// speedup vs baseline: 1.5772x; 1.1559x over previous
#include <cuda_runtime.h>
#include <math.h>
#include <float.h>
#include <stdint.h>

// Problem constants
#define Bv   8
#define Lv   4096
#define LP   4097          // L + 1 (bias token)
#define KDv  512
#define EDv  1024
#define DK   64            // KD / H
#define DV   128           // ED / H
#define BH   64            // B * H
#define KCHUNK   (LP * DK)          // floats per (b,h) key chunk in raw view
#define VCHUNK   (LP * DV)          // floats per (b,h) value chunk in raw view
#define KBATCH   (Lv * KDv)         // real key floats per batch
#define VBATCH   (Lv * EDv)         // real value floats per batch
#define KBATCH4  (KBATCH / 4)
#define NT   16                     // j-tiles for the AV kernel
#define TILE 257                    // ceil(4097 / 16)
#define RPB  128                    // k_scores rows per block
#define SBLK 33                     // ceil(4097 / 128) blocks per bh

// Scratch (allocation-free rule: __device__ globals)
__device__ float g_probs[BH * LP];            // unnormalized exp(scores)
__device__ float g_bsum[BH * SBLK];           // per-block partial sum-of-exp
__device__ float g_partial[BH * NT * DV];     // 512 KB AV partials

__device__ __forceinline__ uint32_t smem_u32(const void* p) {
    uint32_t a;
    asm("{ .reg .u64 tmp; cvta.to.shared.u64 tmp, %1; cvt.u32.u64 %0, tmp; }"
        : "=r"(a) : "l"(p));
    return a;
}
__device__ __forceinline__ void cp_async16(uint32_t dst, const void* src) {
    asm volatile("cp.async.cg.shared.global [%0], [%1], 16;"
                 :: "r"(dst), "l"(src) : "memory");
}

// ---------------------------------------------------------------------------
// Kernel 1: p[bh,j] = exp(dot64(Q[h],K[bh,j,:]) * w[h,j] + bias[h,j])
// grid (SBLK, BH), 128 threads. Stage 128 rows (32KB exactly) via cp.async
// with XOR column swizzle (no register staging, no padding). Thread t then
// computes the full dot64 for row t from smem.
// ---------------------------------------------------------------------------
__global__ void __launch_bounds__(128) k_scores(
        const float* __restrict__ keys,
        const float* __restrict__ k_bias,
        const float* __restrict__ query,
        const float* __restrict__ sw,
        const float* __restrict__ sb) {
    __shared__ float4 sk[RPB * 16];     // 32 KB, XOR-swizzled columns
    __shared__ float4 sq[16];
    __shared__ float  shs[4];

    int bh = blockIdx.y;
    int b  = bh >> 3;
    int h  = bh & 7;
    int t  = threadIdx.x;
    int j0 = blockIdx.x * RPB;

    if (t < 16) sq[t] = *((const float4*)(query + h * DK) + t);

    // stage 128 key rows via cp.async, coalesced, per-float4 bias select
    int fbase4 = (h * KCHUNK) >> 2;
    const float4* kb4 = (const float4*)keys + (size_t)b * KBATCH4;
    const float4* bb4 = (const float4*)k_bias;
    uint32_t sbase = smem_u32(sk);
    #pragma unroll
    for (int i = 0; i < 16; i++) {
        int flat = t + i * 128;         // 0..2047
        int row  = flat >> 4;
        int c4   = flat & 15;
        int jc   = min(j0 + row, LP - 1);
        int f4   = fbase4 + jc * 16 + c4;
        const float4* src = (f4 >= KBATCH4) ? (bb4 + (f4 - KBATCH4)) : (kb4 + f4);
        int phys = row * 16 + ((c4 + row) & 15);   // XOR-free additive swizzle
        cp_async16(sbase + phys * 16, src);
    }
    asm volatile("cp.async.commit_group;");
    asm volatile("cp.async.wait_group 0;");
    __syncthreads();

    // thread t owns row t: dot64 from swizzled smem, 4 accumulators
    int j = j0 + t;
    float e = 0.0f;
    {
        float a0 = 0.f, a1 = 0.f, a2 = 0.f, a3 = 0.f;
        const float4* rowp = sk + t * 16;
        #pragma unroll
        for (int k = 0; k < 16; k += 4) {
            float4 x0 = rowp[(k + t) & 15],     q0 = sq[k];
            float4 x1 = rowp[(k + 1 + t) & 15], q1 = sq[k + 1];
            float4 x2 = rowp[(k + 2 + t) & 15], q2 = sq[k + 2];
            float4 x3 = rowp[(k + 3 + t) & 15], q3 = sq[k + 3];
            a0 += x0.x * q0.x + x0.y * q0.y + x0.z * q0.z + x0.w * q0.w;
            a1 += x1.x * q1.x + x1.y * q1.y + x1.z * q1.z + x1.w * q1.w;
            a2 += x2.x * q2.x + x2.y * q2.y + x2.z * q2.z + x2.w * q2.w;
            a3 += x3.x * q3.x + x3.y * q3.y + x3.z * q3.z + x3.w * q3.w;
        }
        float s = (a0 + a1) + (a2 + a3);
        if (j < LP) {
            int wi = h * LP + j;
            e = expf(s * __ldg(sw + wi) + __ldg(sb + wi));
            g_probs[bh * LP + j] = e;   // coalesced
        }
    }

    // block sum of exps (deterministic)
    int lane = t & 31, warp = t >> 5;
    float wsum = e;
    #pragma unroll
    for (int o = 16; o > 0; o >>= 1)
        wsum += __shfl_xor_sync(0xffffffffu, wsum, o);
    if (lane == 0) shs[warp] = wsum;
    __syncthreads();
    if (t == 0)
        g_bsum[bh * SBLK + blockIdx.x] = (shs[0] + shs[1]) + (shs[2] + shs[3]);
}

// ---------------------------------------------------------------------------
// Kernel 2: partial[bh,tile,d] = sum_{j in tile} p[bh,j] * V[bh,j,d]
// grid (NT, BH), 256 threads = 8 warps; warps interleave rows mod 8.
// Unroll x4 with front-batched loads (MLP=4+ per thread).
// ---------------------------------------------------------------------------
__global__ void k_av(const float* __restrict__ values,
                     const float* __restrict__ v_bias) {
    int tile = blockIdx.x;
    int bh   = blockIdx.y;
    int b = bh >> 3, h = bh & 7;
    int r8 = threadIdx.x >> 5;
    int c  = threadIdx.x & 31;

    const float* p = g_probs + bh * LP;
    int j0 = tile * TILE;
    int j1 = min(j0 + TILE, LP);

    float4 acc = make_float4(0.f, 0.f, 0.f, 0.f);
    int j = j0 + r8;
    for (; j + 24 < j1; j += 32) {
        float p0 = __ldg(p + j);
        float p1 = __ldg(p + j + 8);
        float p2 = __ldg(p + j + 16);
        float p3 = __ldg(p + j + 24);
        int f0 = h * VCHUNK + j * DV;
        int f1 = f0 + 8 * DV, f2 = f0 + 16 * DV, f3 = f0 + 24 * DV;
        const float* r0 = (f0 >= VBATCH) ? (v_bias + (f0 - VBATCH)) : (values + b * VBATCH + f0);
        const float* r1 = (f1 >= VBATCH) ? (v_bias + (f1 - VBATCH)) : (values + b * VBATCH + f1);
        const float* r2 = (f2 >= VBATCH) ? (v_bias + (f2 - VBATCH)) : (values + b * VBATCH + f2);
        const float* r3 = (f3 >= VBATCH) ? (v_bias + (f3 - VBATCH)) : (values + b * VBATCH + f3);
        float4 v0 = __ldcs((const float4*)(r0 + c * 4));
        float4 v1 = __ldcs((const float4*)(r1 + c * 4));
        float4 v2 = __ldcs((const float4*)(r2 + c * 4));
        float4 v3 = __ldcs((const float4*)(r3 + c * 4));
        acc.x += p0 * v0.x + p1 * v1.x + p2 * v2.x + p3 * v3.x;
        acc.y += p0 * v0.y + p1 * v1.y + p2 * v2.y + p3 * v3.y;
        acc.z += p0 * v0.z + p1 * v1.z + p2 * v2.z + p3 * v3.z;
        acc.w += p0 * v0.w + p1 * v1.w + p2 * v2.w + p3 * v3.w;
    }
    for (; j < j1; j += 8) {
        float pa = __ldg(p + j);
        int fa = h * VCHUNK + j * DV;
        const float* ra = (fa >= VBATCH) ? (v_bias + (fa - VBATCH)) : (values + b * VBATCH + fa);
        float4 va = __ldcs((const float4*)(ra + c * 4));
        acc.x += pa * va.x;
        acc.y += pa * va.y;
        acc.z += pa * va.z;
        acc.w += pa * va.w;
    }

    __shared__ float4 red[8][32];
    red[r8][c] = acc;
    __syncthreads();
    if (r8 == 0) {
        float4 a = red[0][c];
        #pragma unroll
        for (int w = 1; w < 8; w++) {
            float4 x = red[w][c];
            a.x += x.x; a.y += x.y; a.z += x.z; a.w += x.w;
        }
        *(float4*)(g_partial + (bh * NT + tile) * DV + c * 4) = a;
    }
}

// ---------------------------------------------------------------------------
// Kernel 3: S[bh] = sum of block sums; reduce NT partials, /S, LayerNorm.
// One block of 256 threads per batch.
// ---------------------------------------------------------------------------
__global__ void k_ln(const float* __restrict__ gamma,
                     const float* __restrict__ beta,
                     float* __restrict__ out) {
    __shared__ float sh_invS[8];
    __shared__ float sh_s[8];
    __shared__ float sh_q[8];
    int b = blockIdx.x;
    int t = threadIdx.x;            // 0..255
    int lane = t & 31, warp = t >> 5;

    // Phase A: per-head sum of exps (warp w -> head w)
    {
        const float* bs = g_bsum + (b * 8 + warp) * SBLK;
        float s = (lane < SBLK) ? bs[lane] : 0.0f;
        if (lane + 32 < SBLK) s += bs[lane + 32];
        #pragma unroll
        for (int o = 16; o > 0; o >>= 1)
            s += __shfl_xor_sync(0xffffffffu, s, o);
        if (lane == 0) sh_invS[warp] = 1.0f / s;
    }
    __syncthreads();

    // Phase B: reduce partials (float4, MLP=NT), normalize, LayerNorm
    int D  = t * 4;
    int hh = t >> 5;
    int dd = D & 127;
    int bh = b * 8 + hh;

    const float* pp = g_partial + bh * (NT * DV) + dd;
    float4 a = make_float4(0.f, 0.f, 0.f, 0.f);
    #pragma unroll
    for (int k = 0; k < NT; k++) {
        float4 x = *(const float4*)(pp + k * DV);
        a.x += x.x; a.y += x.y; a.z += x.z; a.w += x.w;
    }
    float invS = sh_invS[hh];
    a.x *= invS; a.y *= invS; a.z *= invS; a.w *= invS;

    float s = a.x + a.y + a.z + a.w;
    float q = a.x * a.x + a.y * a.y + a.z * a.z + a.w * a.w;
    #pragma unroll
    for (int o = 16; o > 0; o >>= 1) {
        s += __shfl_xor_sync(0xffffffffu, s, o);
        q += __shfl_xor_sync(0xffffffffu, q, o);
    }
    if (lane == 0) { sh_s[warp] = s; sh_q[warp] = q; }
    __syncthreads();
    if (warp == 0 && lane < 8) {
        s = sh_s[lane];
        q = sh_q[lane];
        #pragma unroll
        for (int o = 4; o > 0; o >>= 1) {
            s += __shfl_xor_sync(0x000000ffu, s, o);
            q += __shfl_xor_sync(0x000000ffu, q, o);
        }
        if (lane == 0) { sh_s[0] = s; sh_q[0] = q; }
    }
    __syncthreads();
    float mean = sh_s[0] * (1.0f / EDv);
    float var  = sh_q[0] * (1.0f / EDv) - mean * mean;
    float inv  = rsqrtf(var + 1e-5f);

    float4 gm = *(const float4*)(gamma + D);
    float4 bt = *(const float4*)(beta + D);
    float4 o4;
    o4.x = (a.x - mean) * inv * gm.x + bt.x;
    o4.y = (a.y - mean) * inv * gm.y + bt.y;
    o4.z = (a.z - mean) * inv * gm.z + bt.z;
    o4.w = (a.w - mean) * inv * gm.w + bt.w;
    *(float4*)(out + b * EDv + D) = o4;
}

// ---------------------------------------------------------------------------
// Launch: inputs in metadata order:
// keys, values, query, k_bias, v_bias, softmax_weight, softmax_bias, gamma, beta
// ---------------------------------------------------------------------------
extern "C" void kernel_launch(void* const* d_in, const int* in_sizes, int n_in,
                              void* d_out, int out_size) {
    const float* keys   = (const float*)d_in[0];
    const float* values = (const float*)d_in[1];
    const float* query  = (const float*)d_in[2];
    const float* k_bias = (const float*)d_in[3];
    const float* v_bias = (const float*)d_in[4];
    const float* sw     = (const float*)d_in[5];
    const float* sb     = (const float*)d_in[6];
    const float* gamma  = (const float*)d_in[7];
    const float* beta   = (const float*)d_in[8];
    float* out = (float*)d_out;

    dim3 g1(SBLK, BH);
    k_scores<<<g1, 128>>>(keys, k_bias, query, sw, sb);

    dim3 g2(NT, BH);
    k_av<<<g2, 256>>>(values, v_bias);

    k_ln<<<Bv, 256>>>(gamma, beta, out);
}